// round 15
// baseline (speedup 1.0000x reference)
#include <cuda_runtime.h>
#include <cuda_fp16.h>
#include <cstdint>

// SVC8 5x5 via warp-level mma.sync fp16 implicit GEMM (single fp16, fp32 acc).
//
// M = q (64 spatial cols, ow = 2(q0+q)+c), N = co*2+c (128), K = 6 taps x 16.
//   out[co][4p+r][2(q0+q)+c] = bias[2r+c][co] + sum_k A[q][k] * W[(co,c)][k]
//
// R15: fragment-row permutation row g -> q=2g, row g+8 -> q=2g+1 makes each
// thread's 4 c-fragment floats CONSECUTIVE output columns (4g..4g+3) ->
// epilogue is 1 aligned STG.128 per (mi,nj): store wavefronts halve
// (128B-contiguous per co-row vs 64B segments). To keep the A-fill
// conflict-free with the new 4*gg column coefficient: raw rows at stride 138
// floats (8B cp.async granules) + k-slot -> raw-row permutation RHO so each
// load's four tt-rows occupy disjoint bank windows (quads {0,8,13,5},
// {2,10,3,11},{4,12,1,9},{6,14,7,15}; bank = 10*row + 4*gg mod 32). RHO is
// absorbed into the W-prepack k-mapping -> GEMM result bit-identical.
// W register-hoisted (R13); paired A-fill (R14); direct-STG epilogue.

typedef unsigned int u32;
typedef unsigned long long u64;

#define W_OFF   0                // 96 frags x 256B = 24576
#define A_OFF   24576            // 24 frags x 512B = 12288
#define RAW_OFF 36864            // 2 bufs x 16 rows x 138 floats (552B rows)
#define ROW_B   552
#define BUF_B   8832
#define SMEM_BYTES 54528

// k-slot -> raw row (raw row = tap index ci*5+kh; row 15 = zero pad)
#define RHO_PACK 0xF971EC64B53DA820ull
// per-tt row quads: R0=rho(2tt), R1=rho(2tt+1), R2=rho(2tt+8), R3=rho(2tt+9)
#define Q0_PACK 0x5D80u   // {0,8,13,5}
#define Q1_PACK 0xB3A2u   // {2,10,3,11}
#define Q2_PACK 0x91C4u   // {4,12,1,9}
#define Q3_PACK 0xF7E6u   // {6,14,7,15}

__device__ __forceinline__ u32 smem_u32(const void* p) {
    u32 a;
    asm("{ .reg .u64 t; cvta.to.shared.u64 t, %1; cvt.u32.u64 %0, t; }"
        : "=r"(a) : "l"(p));
    return a;
}

__device__ __forceinline__ u32 pk2(float v0, float v1) {
    __half2 h = __floats2half2_rn(v0, v1);   // v0 -> low half (even k)
    return *(u32*)&h;
}

__device__ __forceinline__ void mma16816(float* d, const u32* a, const u32* b) {
    asm volatile(
        "mma.sync.aligned.m16n8k16.row.col.f32.f16.f16.f32 "
        "{%0,%1,%2,%3}, {%4,%5,%6,%7}, {%8,%9}, {%0,%1,%2,%3};"
        : "+f"(d[0]), "+f"(d[1]), "+f"(d[2]), "+f"(d[3])
        : "r"(a[0]), "r"(a[1]), "r"(a[2]), "r"(a[3]), "r"(b[0]), "r"(b[1]));
}

__global__ void __launch_bounds__(256, 2) svc8_mma_kernel(
    const float* __restrict__ x,
    const float* __restrict__ w,
    const float* __restrict__ bias,
    float* __restrict__ out)
{
    extern __shared__ __align__(16) char smraw[];

    const int tid  = threadIdx.x;
    const int wid  = tid >> 5;
    const int lane = tid & 31;
    const int g    = lane >> 2;
    const int t    = lane & 3;

    const int q0 = blockIdx.x * 64;
    const int p0 = blockIdx.y * 12;
    const int b  = blockIdx.z >> 2;
    const int r  = blockIdx.z & 3;

    const u32 smb = smem_u32(smraw);
    const float* xb = x + (size_t)b * 3 * 720 * 1280;
    const int gcA = 2 * q0 - 4;          // 8B-aligned staging origin

    // ---- zero pad row 15 of both buffers (138 floats each) ----
    for (int k = tid; k < 276; k += 256) {
        int buf = k / 138, cc = k - buf * 138;
        *(float*)(smraw + RAW_OFF + buf * BUF_B + 15 * ROW_B + cc * 4) = 0.f;
    }

    // ---- cp.async staging: 15 rows x 68 x 8B granules ----
    auto stage = [&](int p, int buf) {
        const u32 dst0 = smb + RAW_OFF + (u32)buf * BUF_B;
#pragma unroll
        for (int j = 0; j < 4; j++) {
            int s = tid + j * 256;
            if (j < 3 || s < 1020) {
                int idx = s / 68;
                int m   = s - idx * 68;
                int ci  = idx / 5;
                int kh  = idx - ci * 5;
                int grow  = 4 * p + r - 2 + kh;
                int gcol0 = gcA + 2 * m;
                bool ok = ((unsigned)grow < 720u) && ((unsigned)gcol0 < 1279u);
                const float* src = ok ? (xb + ((size_t)ci * 720 + grow) * 1280 + gcol0)
                                      : xb;
                u32 sz = ok ? 8u : 0u;
                asm volatile("cp.async.ca.shared.global [%0], [%1], 8, %2;"
                             :: "r"(dst0 + (u32)idx * ROW_B + (u32)m * 8u),
                                "l"(src), "r"(sz) : "memory");
            }
        }
        asm volatile("cp.async.commit_group;" ::: "memory");
    };

    // ---- W prepack (once): col-major n-frags, k-slot tap = RHO[k] ----
    for (int s = tid; s < 3072; s += 256) {
        int ln = s & 31, frag = s >> 5;
        int kt = frag >> 4, nf = frag & 15;
        int gg = ln >> 2, tt = ln & 3;
        int n  = nf * 8 + gg;
        int co = n >> 1, c = n & 1;
        int pi = kt & 1, off = (kt >> 1) - 1;
        int kw = 2 * off + pi - c + 2;
        float v[4] = {0.f, 0.f, 0.f, 0.f};
        if (kw >= 0 && kw < 5) {
            const float* wb = w + ((size_t)((2 * r + c) * 64 + co)) * 75 + kw;
#pragma unroll
            for (int j = 0; j < 4; j++) {
                int idx = 2 * tt + ((j >> 1) << 3) + (j & 1);
                int tap = (int)((RHO_PACK >> (4 * idx)) & 15ull);
                if (tap < 15) {
                    int ci = tap / 5, kh = tap - ci * 5;
                    v[j] = wb[ci * 25 + kh * 5];
                }
            }
        }
        u32 b0 = pk2(v[0], v[1]);
        u32 b1 = pk2(v[2], v[3]);
        *(uint2*)(smraw + W_OFF + ((kt * 8 + (nf >> 1)) * 32 + ln) * 16 + (nf & 1) * 8)
            = make_uint2(b0, b1);
    }

    stage(p0, 0);   // prefill buffer 0
    __syncthreads();   // W tile complete

    // ---- warp tiling 32x32: mq = wid&1 (2 m-frags), nq = wid>>1 (4 n-frags) ----
    const int mq = wid & 1, nq = wid >> 1;

    // ---- hoist W fragments into registers (loop-invariant) ----
    uint4 wreg[6][2];
#pragma unroll
    for (int kt = 0; kt < 6; kt++)
#pragma unroll
        for (int jp = 0; jp < 2; jp++)
            wreg[kt][jp] = ((const uint4*)(smraw + W_OFF))[(kt * 8 + nq * 2 + jp) * 32 + lane];

    float bv[4][2];
#pragma unroll
    for (int nj = 0; nj < 4; nj++) {
        int co = (nq * 4 + nj) * 4 + t;
        bv[nj][0] = bias[(2 * r + 0) * 64 + co];
        bv[nj][1] = bias[(2 * r + 1) * 64 + co];
    }

    // ---- p loop ----
#pragma unroll 1
    for (int it = 0; it < 12; it++) {
        const int p   = p0 + it;
        const int buf = it & 1;

        asm volatile("cp.async.wait_group 0;" ::: "memory");
        __syncthreads();   // raw[buf] ready; prev A reads done

        // next-iter staging first: overlaps A-fill + MMA + epilogue
        if (it < 11) stage(p + 1, buf ^ 1);

        // ---- paired A fill (permuted rows): unit (ktp, mi), lane (gg, tt) ----
        // q_a = mi*16 + 2gg (frag row gg), q_b = q_a+1 (frag row gg+8).
        // cols C_a = q_a + ktp + 1, C_b = C_a + 1 (float2 units, stride 69).
        // rows via quads: conflict-free banks (10*row + 4*gg, disjoint windows).
        {
            const float2* pl = (const float2*)(smraw + RAW_OFF + buf * BUF_B);
#pragma unroll
            for (int uu = 0; uu < 2; uu++) {
                if (uu == 0 || tid < 128) {
                    int u  = tid + uu * 256;
                    int ln = u & 31, pu = u >> 5;       // pu in [0,12)
                    int ktp = pu >> 2, mi = pu & 3;
                    int gg = ln >> 2, tt = ln & 3;
                    int sh = 4 * tt;
                    int R0 = (Q0_PACK >> sh) & 15;
                    int R1 = (Q1_PACK >> sh) & 15;
                    int R2 = (Q2_PACK >> sh) & 15;
                    int R3 = (Q3_PACK >> sh) & 15;
                    const float2* rp = pl + (mi * 16 + 2 * gg + ktp + 1);
                    float2 La0 = rp[R0 * 69], Lb0 = rp[R0 * 69 + 1];
                    float2 La1 = rp[R1 * 69], Lb1 = rp[R1 * 69 + 1];
                    float2 La2 = rp[R2 * 69], Lb2 = rp[R2 * 69 + 1];
                    float2 La3 = rp[R3 * 69], Lb3 = rp[R3 * 69 + 1];
                    uint4 av0, av1;
                    av0.x = pk2(La0.x, La1.x);  av1.x = pk2(La0.y, La1.y);  // (q_a, klo)
                    av0.y = pk2(Lb0.x, Lb1.x);  av1.y = pk2(Lb0.y, Lb1.y);  // (q_b, klo)
                    av0.z = pk2(La2.x, La3.x);  av1.z = pk2(La2.y, La3.y);  // (q_a, khi)
                    av0.w = pk2(Lb2.x, Lb3.x);  av1.w = pk2(Lb2.y, Lb3.y);  // (q_b, khi)
                    int f0 = (2 * ktp) * 4 + mi;
                    ((uint4*)(smraw + A_OFF))[f0 * 32 + ln]       = av0;
                    ((uint4*)(smraw + A_OFF))[(f0 + 4) * 32 + ln] = av1;
                }
            }
        }
        __syncthreads();

        // ---- compute: 2 m-frags x 4 n-frags, K = 6x16, W in registers ----
        float d[2][4][4];
#pragma unroll
        for (int mi = 0; mi < 2; mi++)
#pragma unroll
            for (int nj = 0; nj < 4; nj++) {
                d[mi][nj][0] = bv[nj][0];
                d[mi][nj][1] = bv[nj][1];
                d[mi][nj][2] = bv[nj][0];
                d[mi][nj][3] = bv[nj][1];
            }

#pragma unroll
        for (int kt = 0; kt < 6; kt++) {
            u32 bh[4][2];
            bh[0][0] = wreg[kt][0].x; bh[0][1] = wreg[kt][0].y;
            bh[1][0] = wreg[kt][0].z; bh[1][1] = wreg[kt][0].w;
            bh[2][0] = wreg[kt][1].x; bh[2][1] = wreg[kt][1].y;
            bh[3][0] = wreg[kt][1].z; bh[3][1] = wreg[kt][1].w;
#pragma unroll
            for (int mi = 0; mi < 2; mi++) {
                u32 ah[4];
                uint4 va = ((const uint4*)(smraw + A_OFF))[(kt * 4 + mq * 2 + mi) * 32 + lane];
                ah[0] = va.x; ah[1] = va.y; ah[2] = va.z; ah[3] = va.w;
#pragma unroll
                for (int nj = 0; nj < 4; nj++)
                    mma16816(d[mi][nj], ah, bh[nj]);
            }
        }

        // ---- epilogue: one aligned STG.128 per (mi,nj) ----
        // thread (g,t): cols (mq*2+mi)*32 + 4g + {0,1,2,3} = [c(qa,0),c(qa,1),c(qb,0),c(qb,1)]
        {
            const int oh = 4 * p + r;
#pragma unroll
            for (int nj = 0; nj < 4; nj++) {
                int co = (nq * 4 + nj) * 4 + t;
                float* orow = out + (((size_t)(b * 64 + co)) * 720 + oh) * 1280
                            + 2 * q0;
#pragma unroll
                for (int mi = 0; mi < 2; mi++) {
                    int colbase = (mq * 2 + mi) * 32 + 4 * g;
                    float4 v;
                    v.x = d[mi][nj][0];
                    v.y = d[mi][nj][1];
                    v.z = d[mi][nj][2];
                    v.w = d[mi][nj][3];
                    *(float4*)(orow + colbase) = v;
                }
            }
        }
    }
}

extern "C" void kernel_launch(void* const* d_in, const int* in_sizes, int n_in,
                              void* d_out, int out_size)
{
    // x: 2*3*720*1280 = 5529600, w: 8*64*3*5*5 = 38400, b: 8*64 = 512
    const float* x = nullptr;
    const float* w = nullptr;
    const float* bb = nullptr;
    for (int i = 0; i < n_in; i++) {
        if (in_sizes[i] == 5529600)     x  = (const float*)d_in[i];
        else if (in_sizes[i] == 38400)  w  = (const float*)d_in[i];
        else if (in_sizes[i] == 512)    bb = (const float*)d_in[i];
    }
    float* out = (float*)d_out;

    cudaFuncSetAttribute(svc8_mma_kernel,
                         cudaFuncAttributeMaxDynamicSharedMemorySize, SMEM_BYTES);

    dim3 grid(10, 15, 8);
    svc8_mma_kernel<<<grid, 256, SMEM_BYTES>>>(x, w, bb, out);
}